// round 14
// baseline (speedup 1.0000x reference)
#include <cuda_runtime.h>
#include <cuda_bf16.h>

#define NPTS    4096
#define NTOT    8192
#define NPROJ   2000
#define THREADS 512
#define EPT     16          // NTOT / THREADS
#define NBINS   8193        // k + 4096 in [0, 8192]
#define CNT_PAD 8224

__device__ float g_w1[NPROJ];

// ---------------------------------------------------------------------------
// fast atan2: minimax atan(t)/t poly on [0,1], max err ~2e-7 rad
// ---------------------------------------------------------------------------
__device__ __forceinline__ float fast_atan2f(float y, float x)
{
    float ax = fabsf(x), ay = fabsf(y);
    float mx = fmaxf(ax, ay);
    float mn = fminf(ax, ay);
    float t  = __fdividef(mn, fmaxf(mx, 1e-37f));
    float s  = t * t;
    float p  =              -1.1721203e-2f;
    p = fmaf(p, s,           5.2653320e-2f);
    p = fmaf(p, s,          -1.1643287e-1f);
    p = fmaf(p, s,           1.9354346e-1f);
    p = fmaf(p, s,          -3.3262347e-1f);
    p = fmaf(p, s,           9.9997726e-1f);
    float a = p * t;
    a = (ay > ax) ? (1.57079632679489662f - a) : a;
    a = (x < 0.0f) ? (3.14159265358979323846f - a) : a;
    return copysignf(a, y);
}

// ---------------------------------------------------------------------------
// block-wide exclusive scan over 512 threads (16 warps). ws: >=16 entries.
// Leading __syncthreads makes back-to-back reuse of ws safe. NOTE: callers
// must barrier BEFORE computing the per-thread value v if v depends on
// shared memory written by other threads.
// ---------------------------------------------------------------------------
template <typename T>
__device__ __forceinline__ T block_exscan(T v, T* ws)
{
    __syncthreads();
    const unsigned FULL = 0xffffffffu;
    int lane = threadIdx.x & 31;
    int wid  = threadIdx.x >> 5;
    T inc = v;
    #pragma unroll
    for (int o = 1; o < 32; o <<= 1) {
        T n = __shfl_up_sync(FULL, inc, o);
        if (lane >= o) inc += n;
    }
    if (lane == 31) ws[wid] = inc;
    __syncthreads();
    if (wid == 0) {
        T wv = (lane < 16) ? ws[lane] : T(0);
        T winc = wv;
        #pragma unroll
        for (int o = 1; o < 16; o <<= 1) {
            T n = __shfl_up_sync(FULL, winc, o);
            if (lane >= o) winc += n;
        }
        if (lane < 16) ws[lane] = winc - wv;   // exclusive warp bases
    }
    __syncthreads();
    return ws[wid] + (inc - v);
}

template <typename T>
__device__ __forceinline__ T block_reduce_sum(T v, T* ws)
{
    __syncthreads();
    const unsigned FULL = 0xffffffffu;
    int lane = threadIdx.x & 31;
    int wid  = threadIdx.x >> 5;
    #pragma unroll
    for (int o = 16; o > 0; o >>= 1) v += __shfl_down_sync(FULL, v, o);
    if (lane == 0) ws[wid] = v;
    __syncthreads();
    if (threadIdx.x == 0) {
        T s = T(0);
        #pragma unroll
        for (int w = 0; w < 16; w++) s += ws[w];
        ws[0] = s;
    }
    __syncthreads();
    return ws[0];
}

__device__ __forceinline__ int block_reduce_min(int v, int* ws)
{
    __syncthreads();
    const unsigned FULL = 0xffffffffu;
    int lane = threadIdx.x & 31;
    int wid  = threadIdx.x >> 5;
    #pragma unroll
    for (int o = 16; o > 0; o >>= 1) v = min(v, __shfl_down_sync(FULL, v, o));
    if (lane == 0) ws[wid] = v;
    __syncthreads();
    if (threadIdx.x == 0) {
        int s = ws[0];
        #pragma unroll
        for (int w = 1; w < 16; w++) s = min(s, ws[w]);
        ws[0] = s;
    }
    __syncthreads();
    return ws[0];
}

// ---------------------------------------------------------------------------
// Main kernel: one CTA per projection.
// ---------------------------------------------------------------------------
__global__ void __launch_bounds__(THREADS, 2)
sswd_kernel(const float* __restrict__ Xs,
            const float* __restrict__ Xt,
            const float* __restrict__ Us)
{
    extern __shared__ unsigned smem[];
    unsigned* keys  = smem;              // [NTOT]   angle-keys, later k-bins
    unsigned* skeys = keys + NTOT;       // [NTOT]   sorted keys
    unsigned* cnt   = skeys + NTOT;      // [CNT_PAD] counts -> offsets -> float bins
    unsigned* auxu  = cnt + CNT_PAD;     // [32]     scan/reduce scratch

    const int tid = threadIdx.x;
    const int p   = blockIdx.x;

    const float* U = Us + p * 6;         // Us[p, d, k] row-major: [d*2 + k]
    const float u00 = U[0], u01 = U[1];
    const float u10 = U[2], u11 = U[3];
    const float u20 = U[4], u21 = U[5];

    for (int i = tid; i < CNT_PAD; i += THREADS) cnt[i] = 0u;
    __syncthreads();

    // ---- Phase A: compute angle keys + bucket histogram -------------------
    for (int i = tid; i < NTOT; i += THREADS) {
        const float* X;
        unsigned tag;
        if (i < NPTS) { X = Xs + 3 * i;          tag = 0u; }   // source: +1/n
        else          { X = Xt + 3 * (i - NPTS); tag = 1u; }   // target: -1/m
        float x0 = X[0], x1 = X[1], x2 = X[2];
        float p0 = fmaf(u20, x2, fmaf(u10, x1, u00 * x0));
        float p1 = fmaf(u21, x2, fmaf(u11, x1, u01 * x0));
        // angle = (atan2(-p1,-p0) + pi) / (2*pi)  in [0, 1]
        float a = fmaf(fast_atan2f(-p1, -p0), 0.15915494309189535f, 0.5f);
        a = fminf(fmaxf(a, 0.0f), 1.0f);
        unsigned bits = __float_as_uint(a);     // < 2^30 for a in [0,1]
        keys[i] = (bits << 1) | tag;            // tag in LSB (tie: src first)
        int b = min((int)(a * 8192.0f), 8191);
        atomicAdd(&cnt[b], 1u);
    }
    __syncthreads();   // <<< FIX: histogram must be complete before B reads it

    // ---- Phase B: exclusive scan of bucket counts (in place) --------------
    {
        int base = tid * EPT;
        unsigned s = 0;
        #pragma unroll
        for (int j = 0; j < EPT; j++) s += cnt[base + j];
        unsigned ex = block_exscan<unsigned>(s, auxu);
        unsigned run = ex;
        #pragma unroll
        for (int j = 0; j < EPT; j++) {
            unsigned c = cnt[base + j];
            cnt[base + j] = run;
            run += c;
        }
    }
    __syncthreads();

    // ---- Phase C: scatter into buckets (unstable) --------------------------
    for (int i = tid; i < NTOT; i += THREADS) {
        unsigned key = keys[i];
        float a = __uint_as_float(key >> 1);
        int b = min((int)(a * 8192.0f), 8191);
        unsigned pos = atomicAdd(&cnt[b], 1u);  // cnt[b] ends at bucket end
        if (pos < NTOT) skeys[pos] = key;       // defensive clamp
    }
    __syncthreads();

    // ---- Phase D: per-bucket insertion sort (expected size ~1) ------------
    for (int b = tid; b < 8192; b += THREADS) {
        unsigned s0 = (b == 0) ? 0u : cnt[b - 1];
        unsigned e0 = cnt[b];
        for (unsigned i = s0 + 1; i < e0; i++) {
            unsigned key = skeys[i];
            unsigned j = i;
            while (j > s0 && skeys[j - 1] > key) { skeys[j] = skeys[j - 1]; j--; }
            skeys[j] = key;
        }
    }
    __syncthreads();

    // ---- Phase E: k prefix, delta, weighted histogram of k ----------------
    float* bins = (float*)cnt;
    for (int i = tid; i < NBINS; i += THREADS) bins[i] = 0.0f;

    int tsum = 0;
    {
        int base = tid * EPT;
        #pragma unroll
        for (int j = 0; j < EPT; j++) tsum += (int)(skeys[base + j] & 1u);
    }
    int tex = block_exscan<int>(tsum, (int*)auxu);  // 1st barrier covers bin zeroing
    {
        int run  = tex;
        int base = tid * EPT;
        #pragma unroll
        for (int j = 0; j < EPT; j++) {
            int idx = base + j;
            unsigned key = skeys[idx];
            run += (int)(key & 1u);
            int k = (idx + 1) - 2 * run;            // cdf_diff * 4096, exact
            float v  = __uint_as_float(key >> 1);
            float nv = (idx == NTOT - 1) ? 1.0f : __uint_as_float(skeys[idx + 1] >> 1);
            atomicAdd(&bins[k + 4096], nv - v);     // delta-weighted histogram
            keys[idx] = (unsigned)(k + 4096);       // stash k for phase G
        }
    }
    __syncthreads();

    // ---- Phase F: level median = first bin with cum weight >= 0.5 ----------
    float bsum = 0.0f;
    {
        int cbase = tid * 17;
        for (int j = 0; j < 17; j++) {
            int ii = cbase + j;
            if (ii < NBINS) bsum += bins[ii];
        }
    }
    float bex = block_exscan<float>(bsum, (float*)auxu);
    int lessc = 0;
    {
        int cbase = tid * 17;
        float runf = bex;
        for (int j = 0; j < 17; j++) {
            int ii = cbase + j;
            if (ii < NBINS) {
                runf += bins[ii];
                if (runf < 0.5f) lessc++;
            }
        }
    }
    int kIdx = block_reduce_sum<int>(lessc, (int*)auxu);  // first idx with cum>=0.5
    int kMedBin;
    if (kIdx >= NBINS) {
        // total weight < 0.5 (argmin over all-inf -> index 0 -> min cdf_diff)
        int mn = 0x7fffffff;
        for (int i = tid; i < NTOT; i += THREADS) mn = min(mn, (int)keys[i]);
        kMedBin = block_reduce_min(mn, (int*)auxu);
    } else {
        kMedBin = kIdx;
    }

    // ---- Phase G: W1 = (1/4096) * sum delta_i * |k_i - kMed| ---------------
    float s = 0.0f;
    for (int i = tid; i < NTOT; i += THREADS) {
        unsigned key = skeys[i];
        float v  = __uint_as_float(key >> 1);
        float nv = (i == NTOT - 1) ? 1.0f : __uint_as_float(skeys[i + 1] >> 1);
        int kb = (int)keys[i];
        s += (nv - v) * fabsf((float)(kb - kMedBin));
    }
    float tot = block_reduce_sum<float>(s, (float*)auxu);
    if (tid == 0) g_w1[p] = tot * (1.0f / 4096.0f);
}

// ---------------------------------------------------------------------------
// Deterministic final reduction: mean over projections.
// ---------------------------------------------------------------------------
__global__ void sswd_reduce_kernel(float* __restrict__ out)
{
    __shared__ float sh[THREADS];
    int t = threadIdx.x;
    float s = 0.0f;
    for (int i = t; i < NPROJ; i += THREADS) s += g_w1[i];
    sh[t] = s;
    __syncthreads();
    for (int o = THREADS / 2; o > 0; o >>= 1) {
        if (t < o) sh[t] += sh[t + o];
        __syncthreads();
    }
    if (t == 0) out[0] = sh[0] * (1.0f / (float)NPROJ);
}

extern "C" void kernel_launch(void* const* d_in, const int* in_sizes, int n_in,
                              void* d_out, int out_size)
{
    // Identify Us by element count (2000*3*2 = 12000); Xs/Xt are 4096*3 = 12288.
    // (W1 is symmetric in (Xs, Xt), so their relative order is inert anyway.)
    const float* Xs = nullptr;
    const float* Xt = nullptr;
    const float* Us = nullptr;
    for (int i = 0; i < n_in; i++) {
        if (in_sizes[i] == NPROJ * 6) { Us = (const float*)d_in[i]; }
        else if (!Xs)                 { Xs = (const float*)d_in[i]; }
        else                          { Xt = (const float*)d_in[i]; }
    }

    const size_t smem_bytes = (size_t)(NTOT + NTOT + CNT_PAD + 32) * sizeof(unsigned);
    cudaFuncSetAttribute(sswd_kernel,
                         cudaFuncAttributeMaxDynamicSharedMemorySize,
                         (int)smem_bytes);

    sswd_kernel<<<NPROJ, THREADS, smem_bytes>>>(Xs, Xt, Us);
    sswd_reduce_kernel<<<1, THREADS>>>((float*)d_out);
}

// round 15
// speedup vs baseline: 1.2581x; 1.2581x over previous
#include <cuda_runtime.h>
#include <cuda_bf16.h>

#define NPTS    4096
#define NTOT    8192
#define NPROJ   2000
#define THREADS 512
#define EPT     16              // NTOT / THREADS
#define NBINS   8193            // k + 4096 in [0, 8192]
#define CNT_PAD 8224
#define QONE    (1u << 23)      // fixed-point 1.0
#define HALF_Q  (1 << 22)       // fixed-point 0.5

__device__ float g_w1[NPROJ];

// ---------------------------------------------------------------------------
// fast atan2: minimax atan(t)/t poly on [0,1], max err ~2e-7 rad
// ---------------------------------------------------------------------------
__device__ __forceinline__ float fast_atan2f(float y, float x)
{
    float ax = fabsf(x), ay = fabsf(y);
    float mx = fmaxf(ax, ay);
    float mn = fminf(ax, ay);
    float t  = __fdividef(mn, fmaxf(mx, 1e-37f));
    float s  = t * t;
    float p  =              -1.1721203e-2f;
    p = fmaf(p, s,           5.2653320e-2f);
    p = fmaf(p, s,          -1.1643287e-1f);
    p = fmaf(p, s,           1.9354346e-1f);
    p = fmaf(p, s,          -3.3262347e-1f);
    p = fmaf(p, s,           9.9997726e-1f);
    float a = p * t;
    a = (ay > ax) ? (1.57079632679489662f - a) : a;
    a = (x < 0.0f) ? (3.14159265358979323846f - a) : a;
    return copysignf(a, y);
}

// ---------------------------------------------------------------------------
// block-wide exclusive scan over 512 threads (16 warps). ws: >=16 entries.
// Leading __syncthreads also orders prior smem writes before the scan.
// ---------------------------------------------------------------------------
template <typename T>
__device__ __forceinline__ T block_exscan(T v, T* ws)
{
    __syncthreads();
    const unsigned FULL = 0xffffffffu;
    int lane = threadIdx.x & 31;
    int wid  = threadIdx.x >> 5;
    T inc = v;
    #pragma unroll
    for (int o = 1; o < 32; o <<= 1) {
        T n = __shfl_up_sync(FULL, inc, o);
        if (lane >= o) inc += n;
    }
    if (lane == 31) ws[wid] = inc;
    __syncthreads();
    if (wid == 0) {
        T wv = (lane < 16) ? ws[lane] : T(0);
        T winc = wv;
        #pragma unroll
        for (int o = 1; o < 16; o <<= 1) {
            T n = __shfl_up_sync(FULL, winc, o);
            if (lane >= o) winc += n;
        }
        if (lane < 16) ws[lane] = winc - wv;   // exclusive warp bases
    }
    __syncthreads();
    return ws[wid] + (inc - v);
}

template <typename T>
__device__ __forceinline__ T block_reduce_sum(T v, T* ws)
{
    __syncthreads();
    const unsigned FULL = 0xffffffffu;
    int lane = threadIdx.x & 31;
    int wid  = threadIdx.x >> 5;
    #pragma unroll
    for (int o = 16; o > 0; o >>= 1) v += __shfl_down_sync(FULL, v, o);
    if (lane == 0) ws[wid] = v;
    __syncthreads();
    if (threadIdx.x == 0) {
        T s = T(0);
        #pragma unroll
        for (int w = 0; w < 16; w++) s += ws[w];
        ws[0] = s;
    }
    __syncthreads();
    return ws[0];
}

__device__ __forceinline__ int block_reduce_min(int v, int* ws)
{
    __syncthreads();
    const unsigned FULL = 0xffffffffu;
    int lane = threadIdx.x & 31;
    int wid  = threadIdx.x >> 5;
    #pragma unroll
    for (int o = 16; o > 0; o >>= 1) v = min(v, __shfl_down_sync(FULL, v, o));
    if (lane == 0) ws[wid] = v;
    __syncthreads();
    if (threadIdx.x == 0) {
        int s = ws[0];
        #pragma unroll
        for (int w = 1; w < 16; w++) s = min(s, ws[w]);
        ws[0] = s;
    }
    __syncthreads();
    return ws[0];
}

// ---------------------------------------------------------------------------
// Main kernel: one CTA per projection. 24-bit keys: (q23 << 1) | tag.
// ---------------------------------------------------------------------------
__global__ void __launch_bounds__(THREADS, 2)
sswd_kernel(const float* __restrict__ Xs,
            const float* __restrict__ Xt,
            const float* __restrict__ Us)
{
    extern __shared__ unsigned smem[];
    unsigned* keys  = smem;              // [NTOT]
    unsigned* skeys = keys + NTOT;       // [NTOT]  sorted keys
    unsigned* cnt   = skeys + NTOT;      // [CNT_PAD] counts -> offsets -> int bins
    unsigned* auxu  = cnt + CNT_PAD;     // [32] scan/reduce scratch

    const int tid = threadIdx.x;
    const int p   = blockIdx.x;

    const float* U = Us + p * 6;         // Us[p, d, k] row-major
    const float u00 = U[0], u01 = U[1];
    const float u10 = U[2], u11 = U[3];
    const float u20 = U[4], u21 = U[5];

    for (int i = tid; i < CNT_PAD; i += THREADS) cnt[i] = 0u;
    __syncthreads();

    // ---- Phase A: fixed-point angle keys + bucket histogram ---------------
    #pragma unroll
    for (int j = 0; j < 8; j++) {
        int i = tid + j * THREADS;
        float x0 = Xs[3*i], x1 = Xs[3*i+1], x2 = Xs[3*i+2];
        float p0 = fmaf(u20, x2, fmaf(u10, x1, u00 * x0));
        float p1 = fmaf(u21, x2, fmaf(u11, x1, u01 * x0));
        float a  = fmaf(fast_atan2f(-p1, -p0), 0.15915494309189535f, 0.5f);
        a = fminf(fmaxf(a, 0.0f), 1.0f);
        unsigned q = min((unsigned)(a * 8388608.0f), QONE - 1u);
        keys[i] = q << 1;                          // tag 0 = source
        atomicAdd(&cnt[q >> 10], 1u);
    }
    #pragma unroll
    for (int j = 0; j < 8; j++) {
        int i = tid + j * THREADS;
        float x0 = Xt[3*i], x1 = Xt[3*i+1], x2 = Xt[3*i+2];
        float p0 = fmaf(u20, x2, fmaf(u10, x1, u00 * x0));
        float p1 = fmaf(u21, x2, fmaf(u11, x1, u01 * x0));
        float a  = fmaf(fast_atan2f(-p1, -p0), 0.15915494309189535f, 0.5f);
        a = fminf(fmaxf(a, 0.0f), 1.0f);
        unsigned q = min((unsigned)(a * 8388608.0f), QONE - 1u);
        keys[i + NPTS] = (q << 1) | 1u;            // tag 1 = target
        atomicAdd(&cnt[q >> 10], 1u);
    }
    __syncthreads();

    // ---- Phase B: exclusive scan of bucket counts (uint4-vectorized) ------
    {
        uint4* cv = (uint4*)(cnt + tid * EPT);
        uint4 c[4];
        #pragma unroll
        for (int j = 0; j < 4; j++) c[j] = cv[j];
        unsigned s = 0;
        #pragma unroll
        for (int j = 0; j < 4; j++) s += c[j].x + c[j].y + c[j].z + c[j].w;
        unsigned run = block_exscan<unsigned>(s, auxu);
        #pragma unroll
        for (int j = 0; j < 4; j++) {
            unsigned t;
            t = c[j].x; c[j].x = run; run += t;
            t = c[j].y; c[j].y = run; run += t;
            t = c[j].z; c[j].z = run; run += t;
            t = c[j].w; c[j].w = run; run += t;
        }
        #pragma unroll
        for (int j = 0; j < 4; j++) cv[j] = c[j];
    }
    __syncthreads();

    // ---- Phase C: scatter into buckets (unstable; ties carry delta=0) -----
    #pragma unroll
    for (int j = 0; j < EPT; j++) {
        int i = tid + j * THREADS;
        unsigned key = keys[i];
        unsigned pos = atomicAdd(&cnt[key >> 11], 1u);  // bucket = q >> 10
        skeys[pos] = key;
    }
    __syncthreads();

    // ---- Phase D: per-bucket insertion sort (expected size ~1) ------------
    #pragma unroll
    for (int j = 0; j < EPT; j++) {
        int b = tid + j * THREADS;
        unsigned s0 = (b == 0) ? 0u : cnt[b - 1];
        unsigned e0 = cnt[b];
        for (unsigned i = s0 + 1; i < e0; i++) {
            unsigned key = skeys[i];
            unsigned jj  = i;
            while (jj > s0 && skeys[jj - 1] > key) { skeys[jj] = skeys[jj - 1]; jj--; }
            skeys[jj] = key;
        }
    }
    __syncthreads();

    // ---- Phase E: exact integer delta-weighted histogram over k -----------
    int* bins = (int*)cnt;
    for (int i = tid; i < NBINS; i += THREADS) bins[i] = 0;
    // (block_exscan's leading barrier below orders the zeroing before atomics)

    unsigned kv[17];
    const int base = tid * EPT;
    {
        uint4* sv = (uint4*)(skeys + base);
        #pragma unroll
        for (int j = 0; j < 4; j++) {
            uint4 t = sv[j];
            kv[4*j + 0] = t.x; kv[4*j + 1] = t.y;
            kv[4*j + 2] = t.z; kv[4*j + 3] = t.w;
        }
        kv[16] = (tid == THREADS - 1) ? (QONE << 1) : skeys[base + 16]; // pad=1.0
    }
    int tsum = 0;
    #pragma unroll
    for (int j = 0; j < EPT; j++) tsum += (int)(kv[j] & 1u);
    int run  = block_exscan<int>(tsum, (int*)auxu);
    int kmin = 0x7fffffff;
    #pragma unroll
    for (int j = 0; j < EPT; j++) {
        int idx = base + j;
        run += (int)(kv[j] & 1u);
        int kb = (idx + 1) - 2 * run + 4096;               // exact cdf_diff*4096 + 4096
        int dq = (int)(kv[j + 1] >> 1) - (int)(kv[j] >> 1); // exact integer delta
        atomicAdd(&bins[kb], dq);
        kmin = min(kmin, kb);
    }
    __syncthreads();

    // ---- Phase F: level median = first bin with cum weight >= 0.5 ---------
    const int cbase = tid * 17;                 // stride 17: conflict-free
    int bsum = 0;
    for (int j = 0; j < 17; j++) {
        int ii = cbase + j;
        if (ii < NBINS) bsum += bins[ii];
    }
    int bex = block_exscan<int>(bsum, (int*)auxu);
    int lessc = 0;
    {
        int runc = bex;
        for (int j = 0; j < 17; j++) {
            int ii = cbase + j;
            if (ii < NBINS) {
                runc += bins[ii];
                if (runc < HALF_Q) lessc++;
            }
        }
    }
    int kIdx = block_reduce_sum<int>(lessc, (int*)auxu);
    int kMed;
    if (kIdx >= NBINS) {
        // total weight < 0.5 (all-inf argmin -> min cdf_diff); uniform branch
        kMed = block_reduce_min(kmin, (int*)auxu);
    } else {
        kMed = kIdx;
    }

    // ---- Phase G: W1 from bins directly: sum bins[b] * |b - kMed| ----------
    float s = 0.0f;
    for (int j = 0; j < 17; j++) {
        int ii = cbase + j;
        if (ii < NBINS) {
            int bv = bins[ii];
            if (bv) s += (float)bv * fabsf((float)(ii - kMed));
        }
    }
    float tot = block_reduce_sum<float>(s, (float*)auxu);
    if (tid == 0) g_w1[p] = tot * (1.0f / (4096.0f * 8388608.0f));
}

// ---------------------------------------------------------------------------
// Deterministic final reduction: mean over projections.
// ---------------------------------------------------------------------------
__global__ void sswd_reduce_kernel(float* __restrict__ out)
{
    __shared__ float sh[THREADS];
    int t = threadIdx.x;
    float s = 0.0f;
    for (int i = t; i < NPROJ; i += THREADS) s += g_w1[i];
    sh[t] = s;
    __syncthreads();
    for (int o = THREADS / 2; o > 0; o >>= 1) {
        if (t < o) sh[t] += sh[t + o];
        __syncthreads();
    }
    if (t == 0) out[0] = sh[0] * (1.0f / (float)NPROJ);
}

extern "C" void kernel_launch(void* const* d_in, const int* in_sizes, int n_in,
                              void* d_out, int out_size)
{
    // Identify Us by element count (2000*3*2 = 12000); Xs/Xt are 4096*3 = 12288.
    const float* Xs = nullptr;
    const float* Xt = nullptr;
    const float* Us = nullptr;
    for (int i = 0; i < n_in; i++) {
        if (in_sizes[i] == NPROJ * 6) { Us = (const float*)d_in[i]; }
        else if (!Xs)                 { Xs = (const float*)d_in[i]; }
        else                          { Xt = (const float*)d_in[i]; }
    }

    const size_t smem_bytes = (size_t)(NTOT + NTOT + CNT_PAD + 32) * sizeof(unsigned);
    cudaFuncSetAttribute(sswd_kernel,
                         cudaFuncAttributeMaxDynamicSharedMemorySize,
                         (int)smem_bytes);

    sswd_kernel<<<NPROJ, THREADS, smem_bytes>>>(Xs, Xt, Us);
    sswd_reduce_kernel<<<1, THREADS>>>((float*)d_out);
}

// round 16
// speedup vs baseline: 1.2718x; 1.0109x over previous
#include <cuda_runtime.h>
#include <cuda_bf16.h>

#define NPTS    4096
#define NTOT    8192
#define NPROJ   2000
#define THREADS 512
#define QONE    (1u << 23)      // fixed-point 1.0
#define HALF_Q  (1 << 22)       // fixed-point 0.5
#define PAD(b)  ((b) + ((b) >> 4))
#define CNT_WORDS 8720          // pad(8191)=8702; round up

__device__ float g_w1[NPROJ];

// ---------------------------------------------------------------------------
// fast atan2: minimax atan(t)/t poly on [0,1], max err ~2e-7 rad
// ---------------------------------------------------------------------------
__device__ __forceinline__ float fast_atan2f(float y, float x)
{
    float ax = fabsf(x), ay = fabsf(y);
    float mx = fmaxf(ax, ay);
    float mn = fminf(ax, ay);
    float t  = __fdividef(mn, fmaxf(mx, 1e-37f));
    float s  = t * t;
    float p  =              -1.1721203e-2f;
    p = fmaf(p, s,           5.2653320e-2f);
    p = fmaf(p, s,          -1.1643287e-1f);
    p = fmaf(p, s,           1.9354346e-1f);
    p = fmaf(p, s,          -3.3262347e-1f);
    p = fmaf(p, s,           9.9997726e-1f);
    float a = p * t;
    a = (ay > ax) ? (1.57079632679489662f - a) : a;
    a = (x < 0.0f) ? (3.14159265358979323846f - a) : a;
    return copysignf(a, y);
}

// ---------------------------------------------------------------------------
// block-wide primitives (512 threads = 16 warps). ws: >=16 entries.
// Each starts with __syncthreads; callers must still barrier before computing
// inputs that depend on other threads' smem writes.
// ---------------------------------------------------------------------------
template <typename T>
__device__ __forceinline__ T block_exscan(T v, T* ws)
{
    __syncthreads();
    const unsigned FULL = 0xffffffffu;
    int lane = threadIdx.x & 31;
    int wid  = threadIdx.x >> 5;
    T inc = v;
    #pragma unroll
    for (int o = 1; o < 32; o <<= 1) {
        T n = __shfl_up_sync(FULL, inc, o);
        if (lane >= o) inc += n;
    }
    if (lane == 31) ws[wid] = inc;
    __syncthreads();
    if (wid == 0) {
        T wv = (lane < 16) ? ws[lane] : T(0);
        T winc = wv;
        #pragma unroll
        for (int o = 1; o < 16; o <<= 1) {
            T n = __shfl_up_sync(FULL, winc, o);
            if (lane >= o) winc += n;
        }
        if (lane < 16) ws[lane] = winc - wv;   // exclusive warp bases
    }
    __syncthreads();
    return ws[wid] + (inc - v);
}

template <typename T>
__device__ __forceinline__ T block_reduce_sum(T v, T* ws)
{
    __syncthreads();
    const unsigned FULL = 0xffffffffu;
    int lane = threadIdx.x & 31;
    int wid  = threadIdx.x >> 5;
    #pragma unroll
    for (int o = 16; o > 0; o >>= 1) v += __shfl_down_sync(FULL, v, o);
    if (lane == 0) ws[wid] = v;
    __syncthreads();
    if (threadIdx.x == 0) {
        T s = T(0);
        #pragma unroll
        for (int w = 0; w < 16; w++) s += ws[w];
        ws[0] = s;
    }
    __syncthreads();
    return ws[0];
}

__device__ __forceinline__ int block_reduce_min(int v, int* ws)
{
    __syncthreads();
    const unsigned FULL = 0xffffffffu;
    int lane = threadIdx.x & 31;
    int wid  = threadIdx.x >> 5;
    #pragma unroll
    for (int o = 16; o > 0; o >>= 1) v = min(v, __shfl_down_sync(FULL, v, o));
    if (lane == 0) ws[wid] = v;
    __syncthreads();
    if (threadIdx.x == 0) {
        int s = ws[0];
        #pragma unroll
        for (int w = 1; w < 16; w++) s = min(s, ws[w]);
        ws[0] = s;
    }
    __syncthreads();
    return ws[0];
}

__device__ __forceinline__ int block_reduce_max(int v, int* ws)
{
    __syncthreads();
    const unsigned FULL = 0xffffffffu;
    int lane = threadIdx.x & 31;
    int wid  = threadIdx.x >> 5;
    #pragma unroll
    for (int o = 16; o > 0; o >>= 1) v = max(v, __shfl_down_sync(FULL, v, o));
    if (lane == 0) ws[wid] = v;
    __syncthreads();
    if (threadIdx.x == 0) {
        int s = ws[0];
        #pragma unroll
        for (int w = 1; w < 16; w++) s = max(s, ws[w]);
        ws[0] = s;
    }
    __syncthreads();
    return ws[0];
}

// ---------------------------------------------------------------------------
// Main kernel: one CTA per projection.
// keys[i] = (rank<<24) | (q23<<1) | tag.  Padded cnt layout: pad(b)=b+(b>>4).
// ---------------------------------------------------------------------------
__global__ void __launch_bounds__(THREADS, 2)
sswd_kernel(const float* __restrict__ Xs,
            const float* __restrict__ Xt,
            const float* __restrict__ Us)
{
    extern __shared__ unsigned smem[];
    unsigned* keys  = smem;              // [NTOT]     rank|q1
    unsigned* skeys = keys + NTOT;       // [NTOT]     sorted q1 keys
    unsigned* cnt   = skeys + NTOT;      // [CNT_WORDS] padded counts -> offsets
    unsigned* auxu  = cnt + CNT_WORDS;   // [32]       scan/reduce scratch

    const int tid = threadIdx.x;
    const int p   = blockIdx.x;

    const float* U = Us + p * 6;
    const float u00 = U[0], u01 = U[1];
    const float u10 = U[2], u11 = U[3];
    const float u20 = U[4], u21 = U[5];

    for (int i = tid; i < 8704; i += THREADS) cnt[i] = 0u;
    __syncthreads();

    // ---- Phase A: keys + histogram (atomic returns within-bucket rank) ----
    auto point_key = [&](float x0, float x1, float x2, unsigned tag) -> unsigned {
        float p0 = fmaf(u20, x2, fmaf(u10, x1, u00 * x0));
        float p1 = fmaf(u21, x2, fmaf(u11, x1, u01 * x0));
        float a  = fmaf(fast_atan2f(-p1, -p0), 0.15915494309189535f, 0.5f);
        a = fminf(fmaxf(a, 0.0f), 1.0f);
        unsigned q = min((unsigned)(a * 8388608.0f), QONE - 1u);
        unsigned r = atomicAdd(&cnt[PAD(q >> 10)], 1u);
        return (r << 24) | (q << 1) | tag;
    };

    #pragma unroll
    for (int j = 0; j < 4; j++) {                 // 4 pairs of source points
        int pr = tid + j * THREADS;               // pair index, 2048 pairs
        const float* b = Xs + 6 * pr;
        float2 A = *(const float2*)(b);
        float2 B = *(const float2*)(b + 2);
        float2 C = *(const float2*)(b + 4);
        unsigned kA = point_key(A.x, A.y, B.x, 0u);
        unsigned kB = point_key(B.y, C.x, C.y, 0u);
        *(uint2*)(keys + 2 * pr) = make_uint2(kA, kB);
    }
    #pragma unroll
    for (int j = 0; j < 4; j++) {                 // 4 pairs of target points
        int pr = tid + j * THREADS;
        const float* b = Xt + 6 * pr;
        float2 A = *(const float2*)(b);
        float2 B = *(const float2*)(b + 2);
        float2 C = *(const float2*)(b + 4);
        unsigned kA = point_key(A.x, A.y, B.x, 1u);
        unsigned kB = point_key(B.y, C.x, C.y, 1u);
        *(uint2*)(keys + NPTS + 2 * pr) = make_uint2(kA, kB);
    }
    __syncthreads();

    // ---- Phase B: exclusive scan of counts (stride-17, conflict-free) -----
    {
        const int b17 = tid * 17;                 // pad(16*tid + r) = 17*tid + r
        unsigned c[16], s = 0;
        #pragma unroll
        for (int r = 0; r < 16; r++) { c[r] = cnt[b17 + r]; s += c[r]; }
        unsigned run = block_exscan<unsigned>(s, auxu);
        #pragma unroll
        for (int r = 0; r < 16; r++) { unsigned t = c[r]; cnt[b17 + r] = run; run += t; }
    }
    __syncthreads();

    // ---- Phase C: scatter (no atomics: offset + precomputed rank) ---------
    #pragma unroll
    for (int j = 0; j < 16; j++) {
        unsigned key = keys[tid + j * THREADS];
        unsigned q1  = key & 0x00FFFFFFu;         // (q<<1)|tag
        unsigned pos = cnt[PAD(q1 >> 11)] + (key >> 24);
        skeys[pos] = q1;
    }
    __syncthreads();

    // ---- Phase D: per-bucket insertion sort (expected size ~1) ------------
    #pragma unroll
    for (int j = 0; j < 16; j++) {
        int b = tid + j * THREADS;
        unsigned s0 = cnt[PAD(b)];
        unsigned e0 = (b == NTOT - 1) ? (unsigned)NTOT : cnt[PAD(b + 1)];
        for (unsigned i = s0 + 1; i < e0; i++) {
            unsigned key = skeys[i];
            unsigned jj  = i;
            while (jj > s0 && skeys[jj - 1] > key) { skeys[jj] = skeys[jj - 1]; jj--; }
            skeys[jj] = key;
        }
    }
    __syncthreads();

    // ---- Phase E: per-thread (k, dq) packed into registers ----------------
    const int base = tid * 16;
    unsigned kv[17];
    {
        uint4* sv = (uint4*)(skeys + base);
        #pragma unroll
        for (int j = 0; j < 4; j++) {
            uint4 t = sv[j];
            kv[4*j + 0] = t.x; kv[4*j + 1] = t.y;
            kv[4*j + 2] = t.z; kv[4*j + 3] = t.w;
        }
        kv[16] = (tid == THREADS - 1) ? (QONE << 1) : skeys[base + 16];
    }
    unsigned q_first = skeys[0];                  // broadcast read (stable since D)

    int tsum = 0;
    #pragma unroll
    for (int j = 0; j < 16; j++) tsum += (int)(kv[j] & 1u);
    int run = block_exscan<int>(tsum, (int*)auxu);

    unsigned pk[16];                              // (dq<<6) | (k - kc + 16)
    int kc = 0, kmin = 0x7fffffff, kmax = -0x7fffffff;
    #pragma unroll
    for (int j = 0; j < 16; j++) {
        run += (int)(kv[j] & 1u);
        int k = (base + j + 1) - 2 * run + 4096;  // exact cdf_diff*4096 + 4096
        if (j == 0) kc = k;
        unsigned dq = (kv[j + 1] >> 1) - (kv[j] >> 1);
        pk[j] = (dq << 6) | (unsigned)(k - kc + 16);
        kmin = min(kmin, k);
        kmax = max(kmax, k);
    }

    // ---- Phase F: level median via binary search on k ---------------------
    int kminG = block_reduce_min(kmin, (int*)auxu);
    int kmaxG = block_reduce_max(kmax, (int*)auxu);
    int total = (int)(QONE - (q_first >> 1));     // telescoping sum of dq
    int m;
    if (total < HALF_Q) {
        m = kminG;                                // reference's all-inf fallback
    } else {
        int lo = kminG, hi = kmaxG;               // invariant: cum(hi) >= HALF_Q
        while (lo < hi) {
            int mid  = (lo + hi) >> 1;
            int mrel = mid - kc + 16;
            int s = 0;
            #pragma unroll
            for (int j = 0; j < 16; j++) {
                if ((int)(pk[j] & 63u) <= mrel) s += (int)(pk[j] >> 6);
            }
            int cum = block_reduce_sum<int>(s, (int*)auxu);
            if (cum >= HALF_Q) hi = mid; else lo = mid + 1;
        }
        m = lo;
    }

    // ---- Phase G: W1 = (1/(4096*2^23)) * sum dq * |k - m| ------------------
    {
        int mrel = m - kc + 16;
        float fs = 0.0f;
        #pragma unroll
        for (int j = 0; j < 16; j++) {
            float dq = (float)(pk[j] >> 6);
            fs += dq * fabsf((float)((int)(pk[j] & 63u) - mrel));
        }
        float tot = block_reduce_sum<float>(fs, (float*)auxu);
        if (tid == 0) g_w1[p] = tot * (1.0f / (4096.0f * 8388608.0f));
    }
}

// ---------------------------------------------------------------------------
// Deterministic final reduction: mean over projections.
// ---------------------------------------------------------------------------
__global__ void sswd_reduce_kernel(float* __restrict__ out)
{
    __shared__ float sh[THREADS];
    int t = threadIdx.x;
    float s = 0.0f;
    for (int i = t; i < NPROJ; i += THREADS) s += g_w1[i];
    sh[t] = s;
    __syncthreads();
    for (int o = THREADS / 2; o > 0; o >>= 1) {
        if (t < o) sh[t] += sh[t + o];
        __syncthreads();
    }
    if (t == 0) out[0] = sh[0] * (1.0f / (float)NPROJ);
}

extern "C" void kernel_launch(void* const* d_in, const int* in_sizes, int n_in,
                              void* d_out, int out_size)
{
    // Identify Us by element count (2000*3*2 = 12000); Xs/Xt are 4096*3 = 12288.
    const float* Xs = nullptr;
    const float* Xt = nullptr;
    const float* Us = nullptr;
    for (int i = 0; i < n_in; i++) {
        if (in_sizes[i] == NPROJ * 6) { Us = (const float*)d_in[i]; }
        else if (!Xs)                 { Xs = (const float*)d_in[i]; }
        else                          { Xt = (const float*)d_in[i]; }
    }

    const size_t smem_bytes = (size_t)(NTOT + NTOT + CNT_WORDS + 32) * sizeof(unsigned);
    cudaFuncSetAttribute(sswd_kernel,
                         cudaFuncAttributeMaxDynamicSharedMemorySize,
                         (int)smem_bytes);

    sswd_kernel<<<NPROJ, THREADS, smem_bytes>>>(Xs, Xt, Us);
    sswd_reduce_kernel<<<1, THREADS>>>((float*)d_out);
}

// round 17
// speedup vs baseline: 1.2763x; 1.0036x over previous
#include <cuda_runtime.h>
#include <cuda_bf16.h>

#define NPTS    4096
#define NTOT    8192
#define NPROJ   2000
#define THREADS 512
#define QONE    (1u << 23)      // fixed-point 1.0
#define HALF_Q  (1 << 22)       // fixed-point 0.5
#define PAD(b)  ((b) + ((b) >> 4))
#define CNT_WORDS 8720          // pad(8191)=8702; round up

__device__ float g_w1[NPROJ];

// ---------------------------------------------------------------------------
// fast atan2: minimax atan(t)/t poly on [0,1], max err ~2e-7 rad
// ---------------------------------------------------------------------------
__device__ __forceinline__ float fast_atan2f(float y, float x)
{
    float ax = fabsf(x), ay = fabsf(y);
    float mx = fmaxf(ax, ay);
    float mn = fminf(ax, ay);
    float t  = __fdividef(mn, fmaxf(mx, 1e-37f));
    float s  = t * t;
    float p  =              -1.1721203e-2f;
    p = fmaf(p, s,           5.2653320e-2f);
    p = fmaf(p, s,          -1.1643287e-1f);
    p = fmaf(p, s,           1.9354346e-1f);
    p = fmaf(p, s,          -3.3262347e-1f);
    p = fmaf(p, s,           9.9997726e-1f);
    float a = p * t;
    a = (ay > ax) ? (1.57079632679489662f - a) : a;
    a = (x < 0.0f) ? (3.14159265358979323846f - a) : a;
    return copysignf(a, y);
}

// ---------------------------------------------------------------------------
// block-wide primitives (512 threads = 16 warps). ws: >=16 entries.
// Each starts with __syncthreads; callers must still barrier before computing
// inputs that depend on other threads' smem writes.
// ---------------------------------------------------------------------------
template <typename T>
__device__ __forceinline__ T block_exscan(T v, T* ws)
{
    __syncthreads();
    const unsigned FULL = 0xffffffffu;
    int lane = threadIdx.x & 31;
    int wid  = threadIdx.x >> 5;
    T inc = v;
    #pragma unroll
    for (int o = 1; o < 32; o <<= 1) {
        T n = __shfl_up_sync(FULL, inc, o);
        if (lane >= o) inc += n;
    }
    if (lane == 31) ws[wid] = inc;
    __syncthreads();
    if (wid == 0) {
        T wv = (lane < 16) ? ws[lane] : T(0);
        T winc = wv;
        #pragma unroll
        for (int o = 1; o < 16; o <<= 1) {
            T n = __shfl_up_sync(FULL, winc, o);
            if (lane >= o) winc += n;
        }
        if (lane < 16) ws[lane] = winc - wv;   // exclusive warp bases
    }
    __syncthreads();
    return ws[wid] + (inc - v);
}

template <typename T>
__device__ __forceinline__ T block_reduce_sum(T v, T* ws)
{
    __syncthreads();
    const unsigned FULL = 0xffffffffu;
    int lane = threadIdx.x & 31;
    int wid  = threadIdx.x >> 5;
    #pragma unroll
    for (int o = 16; o > 0; o >>= 1) v += __shfl_down_sync(FULL, v, o);
    if (lane == 0) ws[wid] = v;
    __syncthreads();
    if (threadIdx.x == 0) {
        T s = T(0);
        #pragma unroll
        for (int w = 0; w < 16; w++) s += ws[w];
        ws[0] = s;
    }
    __syncthreads();
    return ws[0];
}

__device__ __forceinline__ int block_reduce_min(int v, int* ws)
{
    __syncthreads();
    const unsigned FULL = 0xffffffffu;
    int lane = threadIdx.x & 31;
    int wid  = threadIdx.x >> 5;
    #pragma unroll
    for (int o = 16; o > 0; o >>= 1) v = min(v, __shfl_down_sync(FULL, v, o));
    if (lane == 0) ws[wid] = v;
    __syncthreads();
    if (threadIdx.x == 0) {
        int s = ws[0];
        #pragma unroll
        for (int w = 1; w < 16; w++) s = min(s, ws[w]);
        ws[0] = s;
    }
    __syncthreads();
    return ws[0];
}

__device__ __forceinline__ int block_reduce_max(int v, int* ws)
{
    __syncthreads();
    const unsigned FULL = 0xffffffffu;
    int lane = threadIdx.x & 31;
    int wid  = threadIdx.x >> 5;
    #pragma unroll
    for (int o = 16; o > 0; o >>= 1) v = max(v, __shfl_down_sync(FULL, v, o));
    if (lane == 0) ws[wid] = v;
    __syncthreads();
    if (threadIdx.x == 0) {
        int s = ws[0];
        #pragma unroll
        for (int w = 1; w < 16; w++) s = max(s, ws[w]);
        ws[0] = s;
    }
    __syncthreads();
    return ws[0];
}

// ---------------------------------------------------------------------------
// Main kernel: one CTA per projection.
// keys[i] = (rank<<24) | (q23<<1) | tag.  Padded cnt layout: pad(b)=b+(b>>4).
// ---------------------------------------------------------------------------
__global__ void __launch_bounds__(THREADS, 2)
sswd_kernel(const float* __restrict__ Xs,
            const float* __restrict__ Xt,
            const float* __restrict__ Us)
{
    extern __shared__ unsigned smem[];
    unsigned* keys  = smem;              // [NTOT]     rank|q1
    unsigned* skeys = keys + NTOT;       // [NTOT]     sorted q1 keys
    unsigned* cnt   = skeys + NTOT;      // [CNT_WORDS] padded counts -> offsets
    unsigned* auxu  = cnt + CNT_WORDS;   // [32]       scan/reduce scratch

    const int tid = threadIdx.x;
    const int p   = blockIdx.x;

    const float* U = Us + p * 6;
    const float u00 = U[0], u01 = U[1];
    const float u10 = U[2], u11 = U[3];
    const float u20 = U[4], u21 = U[5];

    for (int i = tid; i < 8704; i += THREADS) cnt[i] = 0u;
    __syncthreads();

    // ---- Phase A: keys + histogram (atomic returns within-bucket rank) ----
    auto point_key = [&](float x0, float x1, float x2, unsigned tag) -> unsigned {
        float p0 = fmaf(u20, x2, fmaf(u10, x1, u00 * x0));
        float p1 = fmaf(u21, x2, fmaf(u11, x1, u01 * x0));
        float a  = fmaf(fast_atan2f(-p1, -p0), 0.15915494309189535f, 0.5f);
        a = fminf(fmaxf(a, 0.0f), 1.0f);
        unsigned q = min((unsigned)(a * 8388608.0f), QONE - 1u);
        unsigned r = atomicAdd(&cnt[PAD(q >> 10)], 1u);
        return (r << 24) | (q << 1) | tag;
    };

    #pragma unroll
    for (int j = 0; j < 4; j++) {                 // 4 pairs of source points
        int pr = tid + j * THREADS;               // pair index, 2048 pairs
        const float* b = Xs + 6 * pr;
        float2 A = *(const float2*)(b);
        float2 B = *(const float2*)(b + 2);
        float2 C = *(const float2*)(b + 4);
        unsigned kA = point_key(A.x, A.y, B.x, 0u);
        unsigned kB = point_key(B.y, C.x, C.y, 0u);
        *(uint2*)(keys + 2 * pr) = make_uint2(kA, kB);
    }
    #pragma unroll
    for (int j = 0; j < 4; j++) {                 // 4 pairs of target points
        int pr = tid + j * THREADS;
        const float* b = Xt + 6 * pr;
        float2 A = *(const float2*)(b);
        float2 B = *(const float2*)(b + 2);
        float2 C = *(const float2*)(b + 4);
        unsigned kA = point_key(A.x, A.y, B.x, 1u);
        unsigned kB = point_key(B.y, C.x, C.y, 1u);
        *(uint2*)(keys + NPTS + 2 * pr) = make_uint2(kA, kB);
    }
    __syncthreads();

    // ---- Phase B: exclusive scan of counts (stride-17, conflict-free) -----
    {
        const int b17 = tid * 17;                 // pad(16*tid + r) = 17*tid + r
        unsigned c[16], s = 0;
        #pragma unroll
        for (int r = 0; r < 16; r++) { c[r] = cnt[b17 + r]; s += c[r]; }
        unsigned run = block_exscan<unsigned>(s, auxu);
        #pragma unroll
        for (int r = 0; r < 16; r++) { unsigned t = c[r]; cnt[b17 + r] = run; run += t; }
    }
    __syncthreads();

    // ---- Phase C: scatter (no atomics: offset + precomputed rank) ---------
    #pragma unroll
    for (int j = 0; j < 16; j++) {
        unsigned key = keys[tid + j * THREADS];
        unsigned q1  = key & 0x00FFFFFFu;         // (q<<1)|tag
        unsigned pos = cnt[PAD(q1 >> 11)] + (key >> 24);
        skeys[pos] = q1;
    }
    __syncthreads();

    // ---- Phase D: per-bucket insertion sort (expected size ~1) ------------
    #pragma unroll
    for (int j = 0; j < 16; j++) {
        int b = tid + j * THREADS;
        unsigned s0 = cnt[PAD(b)];
        unsigned e0 = (b == NTOT - 1) ? (unsigned)NTOT : cnt[PAD(b + 1)];
        for (unsigned i = s0 + 1; i < e0; i++) {
            unsigned key = skeys[i];
            unsigned jj  = i;
            while (jj > s0 && skeys[jj - 1] > key) { skeys[jj] = skeys[jj - 1]; jj--; }
            skeys[jj] = key;
        }
    }
    __syncthreads();

    // ---- Phase E: per-thread (k, dq) packed into registers ----------------
    const int base = tid * 16;
    unsigned kv[17];
    {
        uint4* sv = (uint4*)(skeys + base);
        #pragma unroll
        for (int j = 0; j < 4; j++) {
            uint4 t = sv[j];
            kv[4*j + 0] = t.x; kv[4*j + 1] = t.y;
            kv[4*j + 2] = t.z; kv[4*j + 3] = t.w;
        }
        kv[16] = (tid == THREADS - 1) ? (QONE << 1) : skeys[base + 16];
    }
    unsigned q_first = skeys[0];                  // broadcast read (stable since D)

    int tsum = 0;
    #pragma unroll
    for (int j = 0; j < 16; j++) tsum += (int)(kv[j] & 1u);
    int run = block_exscan<int>(tsum, (int*)auxu);

    unsigned pk[16];                              // (dq<<6) | (k - kc + 16)
    int kc = 0, kmin = 0x7fffffff, kmax = -0x7fffffff;
    #pragma unroll
    for (int j = 0; j < 16; j++) {
        run += (int)(kv[j] & 1u);
        int k = (base + j + 1) - 2 * run + 4096;  // exact cdf_diff*4096 + 4096
        if (j == 0) kc = k;
        unsigned dq = (kv[j + 1] >> 1) - (kv[j] >> 1);
        pk[j] = (dq << 6) | (unsigned)(k - kc + 16);
        kmin = min(kmin, k);
        kmax = max(kmax, k);
    }

    // ---- Phase F: level median via binary search on k ---------------------
    int kminG = block_reduce_min(kmin, (int*)auxu);
    int kmaxG = block_reduce_max(kmax, (int*)auxu);
    int total = (int)(QONE - (q_first >> 1));     // telescoping sum of dq
    int m;
    if (total < HALF_Q) {
        m = kminG;                                // reference's all-inf fallback
    } else {
        int lo = kminG, hi = kmaxG;               // invariant: cum(hi) >= HALF_Q
        while (lo < hi) {
            int mid  = (lo + hi) >> 1;
            int mrel = mid - kc + 16;
            int s = 0;
            #pragma unroll
            for (int j = 0; j < 16; j++) {
                if ((int)(pk[j] & 63u) <= mrel) s += (int)(pk[j] >> 6);
            }
            int cum = block_reduce_sum<int>(s, (int*)auxu);
            if (cum >= HALF_Q) hi = mid; else lo = mid + 1;
        }
        m = lo;
    }

    // ---- Phase G: W1 = (1/(4096*2^23)) * sum dq * |k - m| ------------------
    {
        int mrel = m - kc + 16;
        float fs = 0.0f;
        #pragma unroll
        for (int j = 0; j < 16; j++) {
            float dq = (float)(pk[j] >> 6);
            fs += dq * fabsf((float)((int)(pk[j] & 63u) - mrel));
        }
        float tot = block_reduce_sum<float>(fs, (float*)auxu);
        if (tid == 0) g_w1[p] = tot * (1.0f / (4096.0f * 8388608.0f));
    }
}

// ---------------------------------------------------------------------------
// Deterministic final reduction: mean over projections.
// ---------------------------------------------------------------------------
__global__ void sswd_reduce_kernel(float* __restrict__ out)
{
    __shared__ float sh[THREADS];
    int t = threadIdx.x;
    float s = 0.0f;
    for (int i = t; i < NPROJ; i += THREADS) s += g_w1[i];
    sh[t] = s;
    __syncthreads();
    for (int o = THREADS / 2; o > 0; o >>= 1) {
        if (t < o) sh[t] += sh[t + o];
        __syncthreads();
    }
    if (t == 0) out[0] = sh[0] * (1.0f / (float)NPROJ);
}

extern "C" void kernel_launch(void* const* d_in, const int* in_sizes, int n_in,
                              void* d_out, int out_size)
{
    // Identify Us by element count (2000*3*2 = 12000); Xs/Xt are 4096*3 = 12288.
    const float* Xs = nullptr;
    const float* Xt = nullptr;
    const float* Us = nullptr;
    for (int i = 0; i < n_in; i++) {
        if (in_sizes[i] == NPROJ * 6) { Us = (const float*)d_in[i]; }
        else if (!Xs)                 { Xs = (const float*)d_in[i]; }
        else                          { Xt = (const float*)d_in[i]; }
    }

    const size_t smem_bytes = (size_t)(NTOT + NTOT + CNT_WORDS + 32) * sizeof(unsigned);
    cudaFuncSetAttribute(sswd_kernel,
                         cudaFuncAttributeMaxDynamicSharedMemorySize,
                         (int)smem_bytes);

    sswd_kernel<<<NPROJ, THREADS, smem_bytes>>>(Xs, Xt, Us);
    sswd_reduce_kernel<<<1, THREADS>>>((float*)d_out);
}